// round 2
// baseline (speedup 1.0000x reference)
#include <cuda_runtime.h>

#define S 2048
#define D 64
#define NB 2
#define HH 8
#define NH 16
#define SW 64                      /* S/32 mask words per row */
#define CTX_ELEMS (NB*HH*S*D)      /* 2,097,152 */

// Scratch (allocation-free rule: __device__ globals)
__device__ float    g_Qs[NB*HH*S*D];   // softmaxed Q
__device__ float    g_Ks[NB*HH*S*D];   // softmaxed K
__device__ float    g_l [NB*HH*S];     // row sums of exp
__device__ unsigned g_mb[S*SW];        // packed mask bits

// ---------------------------------------------------------------------------
// softmax over axis=2 (sequence) for Q: per (n,h,d) column of length S
// grid: (NH, 8) ; block 256 = 8 d-cols x 32 s-strips
// ---------------------------------------------------------------------------
__global__ void k_softmax_q(const float* __restrict__ q) {
    int nh = blockIdx.x;
    int dchunk = blockIdx.y;
    int dloc = threadIdx.x & 7;
    int sy = threadIdx.x >> 3;          // 0..31
    int d = dchunk * 8 + dloc;
    const float* base = q + (size_t)nh * S * D + d;
    float sum = 0.f;
    for (int s = sy; s < S; s += 32) sum += __expf(base[(size_t)s * D]);
    __shared__ float red[32][8];
    red[sy][dloc] = sum;
    __syncthreads();
    for (int off = 16; off > 0; off >>= 1) {
        if (sy < off) red[sy][dloc] += red[sy + off][dloc];
        __syncthreads();
    }
    float iv = 1.f / red[0][dloc];
    float* out = g_Qs + (size_t)nh * S * D + d;
    for (int s = sy; s < S; s += 32)
        out[(size_t)s * D] = __expf(base[(size_t)s * D]) * iv;
}

// ---------------------------------------------------------------------------
// softmax over axis=1 (heads) for K: per (n,s,d), 8 strided values
// ---------------------------------------------------------------------------
__global__ void k_softmax_k(const float* __restrict__ k) {
    int idx = blockIdx.x * blockDim.x + threadIdx.x;   // 0 .. NB*S*D-1
    if (idx >= NB * S * D) return;
    int n = idx / (S * D);
    int sd = idx - n * (S * D);
    const float* p = k + (size_t)n * HH * S * D + sd;
    float* o = g_Ks + (size_t)n * HH * S * D + sd;
    float e[HH];
    float sum = 0.f;
#pragma unroll
    for (int h = 0; h < HH; h++) { e[h] = __expf(p[(size_t)h * S * D]); sum += e[h]; }
    float iv = 1.f / sum;
#pragma unroll
    for (int h = 0; h < HH; h++) o[(size_t)h * S * D] = e[h] * iv;
}

// ---------------------------------------------------------------------------
// pack the int32 mask into bits: g_mb[q*SW + w] bit b = (mask[q, w*32+b] != 0)
// ---------------------------------------------------------------------------
__global__ void k_pack_mask(const int* __restrict__ m) {
    int idx = blockIdx.x * blockDim.x + threadIdx.x;   // S*SW = 131072
    if (idx >= S * SW) return;
    int qq = idx >> 6;
    int w = idx & 63;
    const int* p = m + (size_t)qq * S + w * 32;
    unsigned bits = 0;
#pragma unroll
    for (int b = 0; b < 32; b++) if (p[b] != 0) bits |= (1u << b);
    g_mb[idx] = bits;
}

// ---------------------------------------------------------------------------
// Stage 1: logits = Qs @ Ks^T, e = exp(logit)*maskbit, write UNNORMALIZED e
// to the attn output region, accumulate per-row sums l.
// grid: (32 q-tiles, 16 nh), block 256 (16x16, each thread 4x4)
// ---------------------------------------------------------------------------
__global__ void __launch_bounds__(256) k_attn1(float* __restrict__ attn) {
    int nh = blockIdx.y;
    int q0 = blockIdx.x * 64;
    int tid = threadIdx.x;
    int tx = tid & 15, ty = tid >> 4;

    __shared__ float Qt[64][68];   // Qt[d][q]
    __shared__ float Kt[64][68];   // Kt[d][k]
    __shared__ float red[16][65];  // red[tx][q]

    const float* Qg = g_Qs + (size_t)nh * S * D;
    const float* Kg = g_Ks + (size_t)nh * S * D;
    float* attnb = attn + (size_t)nh * S * S;

#pragma unroll
    for (int i = 0; i < 16; i++) {
        int lin = i * 256 + tid;
        int r = lin >> 6, d = lin & 63;
        Qt[d][r] = Qg[(size_t)(q0 + r) * D + d];
    }

    float lp[4] = {0.f, 0.f, 0.f, 0.f};

    for (int kt = 0; kt < 32; kt++) {
#pragma unroll
        for (int i = 0; i < 16; i++) {
            int lin = i * 256 + tid;
            int r = lin >> 6, d = lin & 63;
            Kt[d][r] = Kg[(size_t)(kt * 64 + r) * D + d];
        }
        __syncthreads();

        float acc[4][4];
#pragma unroll
        for (int i = 0; i < 4; i++)
#pragma unroll
            for (int j = 0; j < 4; j++) acc[i][j] = 0.f;

#pragma unroll 4
        for (int d = 0; d < 64; d++) {
            float4 a = *(const float4*)&Qt[d][ty * 4];
            float4 b = *(const float4*)&Kt[d][tx * 4];
            acc[0][0] += a.x * b.x; acc[0][1] += a.x * b.y; acc[0][2] += a.x * b.z; acc[0][3] += a.x * b.w;
            acc[1][0] += a.y * b.x; acc[1][1] += a.y * b.y; acc[1][2] += a.y * b.z; acc[1][3] += a.y * b.w;
            acc[2][0] += a.z * b.x; acc[2][1] += a.z * b.y; acc[2][2] += a.z * b.z; acc[2][3] += a.z * b.w;
            acc[3][0] += a.w * b.x; acc[3][1] += a.w * b.y; acc[3][2] += a.w * b.z; acc[3][3] += a.w * b.w;
        }

        unsigned shamt = (tx & 7) * 4;
#pragma unroll
        for (int i = 0; i < 4; i++) {
            int qg = q0 + ty * 4 + i;
            unsigned mw = g_mb[(size_t)qg * SW + kt * 2 + (tx >> 3)];
            float4 ev;
            ev.x = ((mw >> (shamt + 0)) & 1u) ? __expf(acc[i][0]) : 0.f;
            ev.y = ((mw >> (shamt + 1)) & 1u) ? __expf(acc[i][1]) : 0.f;
            ev.z = ((mw >> (shamt + 2)) & 1u) ? __expf(acc[i][2]) : 0.f;
            ev.w = ((mw >> (shamt + 3)) & 1u) ? __expf(acc[i][3]) : 0.f;
            lp[i] += ev.x + ev.y + ev.z + ev.w;
            *(float4*)&attnb[(size_t)qg * S + kt * 64 + tx * 4] = ev;
        }
        __syncthreads();
    }

#pragma unroll
    for (int i = 0; i < 4; i++) red[tx][ty * 4 + i] = lp[i];
    __syncthreads();
    if (tid < 64) {
        float s = 0.f;
#pragma unroll
        for (int t = 0; t < 16; t++) s += red[t][tid];
        g_l[(size_t)nh * S + q0 + tid] = s;
    }
}

// ---------------------------------------------------------------------------
// Stage 2: normalize attn in place (w = e / l) and context = W @ V
// grid: (32 q-tiles, 16 nh), block 256 (16x16, each thread 4q x 4d)
// ---------------------------------------------------------------------------
__global__ void __launch_bounds__(256) k_attn2(float* __restrict__ attn,
                                               const float* __restrict__ v,
                                               float* __restrict__ ctx) {
    int nh = blockIdx.y;
    int q0 = blockIdx.x * 64;
    int tid = threadIdx.x;
    int tx = tid & 15, ty = tid >> 4;

    __shared__ float Wt[64][68];   // Wt[k][q]
    __shared__ float Vt[64][68];   // Vt[k][d]
    __shared__ float invl[64];

    if (tid < 64) {
        float l = g_l[(size_t)nh * S + q0 + tid];
        invl[tid] = (l > 0.f) ? 1.f / l : 0.f;
    }
    __syncthreads();

    const float* Vg = v + (size_t)nh * S * D;
    float* attnb = attn + (size_t)nh * S * S;

    float C[4][4];
#pragma unroll
    for (int i = 0; i < 4; i++)
#pragma unroll
        for (int j = 0; j < 4; j++) C[i][j] = 0.f;

    for (int kt = 0; kt < 32; kt++) {
        // load e tile, normalize, write back, transpose into Wt[k][q]
#pragma unroll
        for (int i = 0; i < 4; i++) {
            int lin = i * 256 + tid;       // over 1024 float4s
            int r = lin >> 4;              // q row 0..63
            int c4 = (lin & 15) * 4;       // k col base
            float* p = &attnb[(size_t)(q0 + r) * S + kt * 64 + c4];
            float4 e = *(float4*)p;
            float iv = invl[r];
            e.x *= iv; e.y *= iv; e.z *= iv; e.w *= iv;
            *(float4*)p = e;
            Wt[c4 + 0][r] = e.x; Wt[c4 + 1][r] = e.y;
            Wt[c4 + 2][r] = e.z; Wt[c4 + 3][r] = e.w;
        }
        // load V tile [k][d]
#pragma unroll
        for (int i = 0; i < 4; i++) {
            int lin = i * 256 + tid;
            int r = lin >> 4;              // k 0..63
            int c4 = (lin & 15) * 4;       // d
            *(float4*)&Vt[r][c4] = *(const float4*)&Vg[(size_t)(kt * 64 + r) * D + c4];
        }
        __syncthreads();

#pragma unroll 4
        for (int kk = 0; kk < 64; kk++) {
            float4 a = *(const float4*)&Wt[kk][ty * 4];
            float4 b = *(const float4*)&Vt[kk][tx * 4];
            C[0][0] += a.x * b.x; C[0][1] += a.x * b.y; C[0][2] += a.x * b.z; C[0][3] += a.x * b.w;
            C[1][0] += a.y * b.x; C[1][1] += a.y * b.y; C[1][2] += a.y * b.z; C[1][3] += a.y * b.w;
            C[2][0] += a.z * b.x; C[2][1] += a.z * b.y; C[2][2] += a.z * b.z; C[2][3] += a.z * b.w;
            C[3][0] += a.w * b.x; C[3][1] += a.w * b.y; C[3][2] += a.w * b.z; C[3][3] += a.w * b.w;
        }
        __syncthreads();
    }

#pragma unroll
    for (int i = 0; i < 4; i++) {
        float4 o = make_float4(C[i][0], C[i][1], C[i][2], C[i][3]);
        *(float4*)&ctx[(size_t)((size_t)nh * S + q0 + ty * 4 + i) * D + tx * 4] = o;
    }
}

// ---------------------------------------------------------------------------
extern "C" void kernel_launch(void* const* d_in, const int* in_sizes, int n_in,
                              void* d_out, int out_size) {
    const float* q = (const float*)d_in[0];
    const float* k = (const float*)d_in[1];
    const float* v = (const float*)d_in[2];
    const int*   m = (const int*)d_in[3];

    float* ctx  = (float*)d_out;
    float* attn = (float*)d_out + CTX_ELEMS;

    k_softmax_q<<<dim3(NH, 8), 256>>>(q);
    k_softmax_k<<<(NB * S * D + 255) / 256, 256>>>(k);
    k_pack_mask<<<(S * SW + 255) / 256, 256>>>(m);
    k_attn1<<<dim3(S / 64, NH), 256>>>(attn);
    k_attn2<<<dim3(S / 64, NH), 256>>>(attn, v, ctx);
}

// round 6
// speedup vs baseline: 2.3834x; 2.3834x over previous
#include <cuda_runtime.h>
#include <cuda_bf16.h>
#include <cstdint>

#define S 2048
#define D 64
#define NB 2
#define HH 8
#define NH 16
#define SW 64                      /* S/32 mask words per row */
#define CTX_ELEMS (NB*HH*S*D)

// ---------------- scratch (__device__ globals; no allocations) --------------
__device__ __nv_bfloat16 g_Qb[NB*HH*S*D];   // softmaxed Q, bf16
__device__ __nv_bfloat16 g_Kb[NB*HH*S*D];   // softmaxed K, bf16
__device__ unsigned      g_mb[S*SW];        // packed mask bits

#define SWZ(o) ((o) ^ (((o) >> 3) & 0x70))

__device__ __forceinline__ uint32_t smem_u32(const void* p) {
    uint32_t a;
    asm("{ .reg .u64 t; cvta.to.shared.u64 t, %1; cvt.u32.u64 %0, t; }" : "=r"(a) : "l"(p));
    return a;
}
__device__ __forceinline__ void ldsm4(uint32_t* r, uint32_t a) {
    asm volatile("ldmatrix.sync.aligned.m8n8.x4.shared.b16 {%0,%1,%2,%3}, [%4];"
                 : "=r"(r[0]), "=r"(r[1]), "=r"(r[2]), "=r"(r[3]) : "r"(a));
}
__device__ __forceinline__ void ldsm4t(uint32_t* r, uint32_t a) {
    asm volatile("ldmatrix.sync.aligned.m8n8.x4.trans.shared.b16 {%0,%1,%2,%3}, [%4];"
                 : "=r"(r[0]), "=r"(r[1]), "=r"(r[2]), "=r"(r[3]) : "r"(a));
}
__device__ __forceinline__ void mma_bf(float* c, const uint32_t* a, const uint32_t* b) {
    asm volatile("mma.sync.aligned.m16n8k16.row.col.f32.bf16.bf16.f32 "
                 "{%0,%1,%2,%3}, {%4,%5,%6,%7}, {%8,%9}, {%0,%1,%2,%3};"
                 : "+f"(c[0]), "+f"(c[1]), "+f"(c[2]), "+f"(c[3])
                 : "r"(a[0]), "r"(a[1]), "r"(a[2]), "r"(a[3]), "r"(b[0]), "r"(b[1]));
}
__device__ __forceinline__ uint32_t pack_bf(__nv_bfloat16 a, __nv_bfloat16 b) {
    __nv_bfloat162 p = __halves2bfloat162(a, b);
    return *(uint32_t*)&p;
}

// ---------------------------------------------------------------------------
// softmax over axis=2 (sequence) for Q -> bf16
// ---------------------------------------------------------------------------
__global__ void k_softmax_q(const float* __restrict__ q) {
    int nh = blockIdx.x, dchunk = blockIdx.y;
    int dloc = threadIdx.x & 7, sy = threadIdx.x >> 3;
    int d = dchunk * 8 + dloc;
    const float* base = q + (size_t)nh * S * D + d;
    float sum = 0.f;
    for (int s = sy; s < S; s += 32) sum += __expf(base[(size_t)s * D]);
    __shared__ float red[32][8];
    red[sy][dloc] = sum;
    __syncthreads();
    for (int off = 16; off > 0; off >>= 1) {
        if (sy < off) red[sy][dloc] += red[sy + off][dloc];
        __syncthreads();
    }
    float iv = 1.f / red[0][dloc];
    __nv_bfloat16* out = g_Qb + (size_t)nh * S * D + d;
    for (int s = sy; s < S; s += 32)
        out[(size_t)s * D] = __float2bfloat16(__expf(base[(size_t)s * D]) * iv);
}

// ---------------------------------------------------------------------------
// softmax over axis=1 (heads) for K -> bf16
// ---------------------------------------------------------------------------
__global__ void k_softmax_k(const float* __restrict__ k) {
    int idx = blockIdx.x * blockDim.x + threadIdx.x;
    if (idx >= NB * S * D) return;
    int n = idx / (S * D);
    int sd = idx - n * (S * D);
    const float* p = k + (size_t)n * HH * S * D + sd;
    __nv_bfloat16* o = g_Kb + (size_t)n * HH * S * D + sd;
    float e[HH]; float sum = 0.f;
#pragma unroll
    for (int h = 0; h < HH; h++) { e[h] = __expf(p[(size_t)h * S * D]); sum += e[h]; }
    float iv = 1.f / sum;
#pragma unroll
    for (int h = 0; h < HH; h++) o[(size_t)h * S * D] = __float2bfloat16(e[h] * iv);
}

// ---------------------------------------------------------------------------
// pack mask bits
// ---------------------------------------------------------------------------
__global__ void k_pack_mask(const int* __restrict__ m) {
    int idx = blockIdx.x * blockDim.x + threadIdx.x;
    if (idx >= S * SW) return;
    int qq = idx >> 6, w = idx & 63;
    const int* p = m + (size_t)qq * S + w * 32;
    unsigned bits = 0;
#pragma unroll
    for (int b = 0; b < 32; b++) if (p[b] != 0) bits |= (1u << b);
    g_mb[idx] = bits;
}

// ---------------------------------------------------------------------------
// fused attention: per (128-row q-tile, nh)
//   pass1: GEMM1 (HMMA bf16) + masked exp -> row sums
//   pass2: GEMM1 again, normalize, store attn fp32, split-bf16 GEMM2 -> ctx
// ---------------------------------------------------------------------------
#define O_INVL 0
#define O_MB   512
#define O_Q    3072
#define O_K    (O_Q  + 16384)
#define O_VH   (O_K  + 16384)
#define O_VL   (O_VH + 16384)
#define SMEM_T (O_VL + 16384)   /* 68608 bytes */

__global__ void __launch_bounds__(256, 1) k_attn(const float* __restrict__ v,
                                                 float* __restrict__ attn,
                                                 float* __restrict__ ctx) {
    extern __shared__ char smem[];
    const int tid = threadIdx.x, wid = tid >> 5, lid = tid & 31;
    const int g = lid >> 2, t = lid & 3;
    const int nh = blockIdx.y, q0 = blockIdx.x * 128;
    const uint32_t sb = smem_u32(smem);
    float* invl = (float*)(smem + O_INVL);

    const __nv_bfloat16* Qg = g_Qb + ((size_t)nh * S + q0) * D;
    const __nv_bfloat16* Kg = g_Kb + (size_t)nh * S * D;
    const float* Vg = v + (size_t)nh * S * D;
    float* attnb = attn + (size_t)nh * S * S;

    // ---- load Q tile (128x64 bf16, SW128-swizzled rows of 128B) ----
#pragma unroll
    for (int i = 0; i < 4; i++) {
        int idx = i * 256 + tid;
        int r = idx >> 3, s16 = idx & 7;
        *(uint4*)(smem + O_Q + SWZ(r * 128 + s16 * 16)) =
            *(const uint4*)(Qg + (size_t)r * 64 + s16 * 8);
    }
    __syncthreads();

    // hoist A fragments (rows 16*wid..+15, 4 k16 steps)
    uint32_t aQ[4][4];
#pragma unroll
    for (int kk = 0; kk < 4; kk++) {
        int rl = 16 * wid + (lid & 7) + (lid & 8);
        int c16 = kk * 2 + (lid >> 4);
        ldsm4(aQ[kk], sb + O_Q + SWZ(rl * 128 + c16 * 16));
    }

    const int r0l = 16 * wid + g, r1l = r0l + 8;

    // ================= pass 1: row sums =================
    float rs0 = 0.f, rs1 = 0.f;
    for (int kt = 0; kt < 16; kt++) {
#pragma unroll
        for (int i = 0; i < 4; i++) {
            int idx = i * 256 + tid;
            int r = idx >> 3, s16 = idx & 7;
            *(uint4*)(smem + O_K + SWZ(r * 128 + s16 * 16)) =
                *(const uint4*)(Kg + (size_t)(kt * 128 + r) * 64 + s16 * 8);
        }
        if (tid < 128)
            *(uint4*)(smem + O_MB + tid * 16) =
                *(const uint4*)(g_mb + (size_t)(q0 + tid) * SW + kt * 4);
        __syncthreads();

        float acc[16][4];
#pragma unroll
        for (int f = 0; f < 16; f++) { acc[f][0] = acc[f][1] = acc[f][2] = acc[f][3] = 0.f; }
#pragma unroll
        for (int f = 0; f < 16; f++) {
#pragma unroll
            for (int kp = 0; kp < 2; kp++) {
                uint32_t b[4];
                ldsm4(b, sb + O_K + SWZ((f * 8 + (lid & 7)) * 128 + (kp * 4 + (lid >> 3)) * 16));
                mma_bf(acc[f], aQ[2 * kp], b);
                mma_bf(acc[f], aQ[2 * kp + 1], b + 2);
            }
        }
        uint4 mw0 = *(uint4*)(smem + O_MB + r0l * 16);
        uint4 mw1 = *(uint4*)(smem + O_MB + r1l * 16);
        unsigned m0a[4] = {mw0.x, mw0.y, mw0.z, mw0.w};
        unsigned m1a[4] = {mw1.x, mw1.y, mw1.z, mw1.w};
#pragma unroll
        for (int f = 0; f < 16; f++) {
            int bit = 8 * (f & 3) + 2 * t;
            unsigned w0 = m0a[f >> 2], w1 = m1a[f >> 2];
            if ((w0 >> bit) & 1)       rs0 += __expf(acc[f][0]);
            if ((w0 >> (bit + 1)) & 1) rs0 += __expf(acc[f][1]);
            if ((w1 >> bit) & 1)       rs1 += __expf(acc[f][2]);
            if ((w1 >> (bit + 1)) & 1) rs1 += __expf(acc[f][3]);
        }
        __syncthreads();
    }
    rs0 += __shfl_xor_sync(0xffffffffu, rs0, 1);
    rs0 += __shfl_xor_sync(0xffffffffu, rs0, 2);
    rs1 += __shfl_xor_sync(0xffffffffu, rs1, 1);
    rs1 += __shfl_xor_sync(0xffffffffu, rs1, 2);
    if (t == 0) {
        invl[r0l] = rs0 > 0.f ? 1.f / rs0 : 0.f;
        invl[r1l] = rs1 > 0.f ? 1.f / rs1 : 0.f;
    }
    __syncthreads();
    const float iv0 = invl[r0l], iv1 = invl[r1l];

    // ================= pass 2: recompute + normalize + GEMM2 =================
    float ctxa[8][4];
#pragma unroll
    for (int n = 0; n < 8; n++) { ctxa[n][0] = ctxa[n][1] = ctxa[n][2] = ctxa[n][3] = 0.f; }

    for (int kt = 0; kt < 16; kt++) {
#pragma unroll
        for (int i = 0; i < 4; i++) {
            int idx = i * 256 + tid;
            int r = idx >> 3, s16 = idx & 7;
            *(uint4*)(smem + O_K + SWZ(r * 128 + s16 * 16)) =
                *(const uint4*)(Kg + (size_t)(kt * 128 + r) * 64 + s16 * 8);
        }
        // V tile fp32 -> split bf16 (hi/lo)
#pragma unroll
        for (int i = 0; i < 4; i++) {
            int idx = i * 256 + tid;
            int r = idx >> 3, s16 = idx & 7;
            const float* vp = Vg + (size_t)(kt * 128 + r) * 64 + s16 * 8;
            float4 f0 = *(const float4*)vp;
            float4 f1 = *(const float4*)(vp + 4);
            float fv[8] = {f0.x, f0.y, f0.z, f0.w, f1.x, f1.y, f1.z, f1.w};
            uint4 vh, vl;
#pragma unroll
            for (int e2 = 0; e2 < 4; e2++) {
                __nv_bfloat16 h0 = __float2bfloat16(fv[2 * e2]);
                __nv_bfloat16 h1 = __float2bfloat16(fv[2 * e2 + 1]);
                ((uint32_t*)&vh)[e2] = pack_bf(h0, h1);
                __nv_bfloat162 lo = __floats2bfloat162_rn(fv[2 * e2] - __bfloat162float(h0),
                                                          fv[2 * e2 + 1] - __bfloat162float(h1));
                ((uint32_t*)&vl)[e2] = *(uint32_t*)&lo;
            }
            *(uint4*)(smem + O_VH + SWZ(r * 128 + s16 * 16)) = vh;
            *(uint4*)(smem + O_VL + SWZ(r * 128 + s16 * 16)) = vl;
        }
        if (tid < 128)
            *(uint4*)(smem + O_MB + tid * 16) =
                *(const uint4*)(g_mb + (size_t)(q0 + tid) * SW + kt * 4);
        __syncthreads();

        float acc[16][4];
#pragma unroll
        for (int f = 0; f < 16; f++) { acc[f][0] = acc[f][1] = acc[f][2] = acc[f][3] = 0.f; }
#pragma unroll
        for (int f = 0; f < 16; f++) {
#pragma unroll
            for (int kp = 0; kp < 2; kp++) {
                uint32_t b[4];
                ldsm4(b, sb + O_K + SWZ((f * 8 + (lid & 7)) * 128 + (kp * 4 + (lid >> 3)) * 16));
                mma_bf(acc[f], aQ[2 * kp], b);
                mma_bf(acc[f], aQ[2 * kp + 1], b + 2);
            }
        }

        // epilogue: masked exp, normalize, store fp32 attn, build split-bf16 W frags
        uint4 mw0 = *(uint4*)(smem + O_MB + r0l * 16);
        uint4 mw1 = *(uint4*)(smem + O_MB + r1l * 16);
        unsigned m0a[4] = {mw0.x, mw0.y, mw0.z, mw0.w};
        unsigned m1a[4] = {mw1.x, mw1.y, mw1.z, mw1.w};
        uint32_t wh[16][2], wl[16][2];
#pragma unroll
        for (int f = 0; f < 16; f++) {
            int bit = 8 * (f & 3) + 2 * t;
            unsigned w0 = m0a[f >> 2], w1 = m1a[f >> 2];
            float e0 = ((w0 >> bit) & 1)       ? __expf(acc[f][0]) * iv0 : 0.f;
            float e1 = ((w0 >> (bit + 1)) & 1) ? __expf(acc[f][1]) * iv0 : 0.f;
            float e2 = ((w1 >> bit) & 1)       ? __expf(acc[f][2]) * iv1 : 0.f;
            float e3 = ((w1 >> (bit + 1)) & 1) ? __expf(acc[f][3]) * iv1 : 0.f;
            int c = kt * 128 + 8 * f + 2 * t;
            *(float2*)&attnb[(size_t)(q0 + r0l) * S + c] = make_float2(e0, e1);
            *(float2*)&attnb[(size_t)(q0 + r1l) * S + c] = make_float2(e2, e3);
            __nv_bfloat16 h0 = __float2bfloat16(e0), h1 = __float2bfloat16(e1);
            __nv_bfloat16 h2 = __float2bfloat16(e2), h3 = __float2bfloat16(e3);
            wh[f][0] = pack_bf(h0, h1);
            wh[f][1] = pack_bf(h2, h3);
            __nv_bfloat162 l01 = __floats2bfloat162_rn(e0 - __bfloat162float(h0),
                                                       e1 - __bfloat162float(h1));
            __nv_bfloat162 l23 = __floats2bfloat162_rn(e2 - __bfloat162float(h2),
                                                       e3 - __bfloat162float(h3));
            wl[f][0] = *(uint32_t*)&l01;
            wl[f][1] = *(uint32_t*)&l23;
        }

        // GEMM2: ctx += W @ V  (split: Wh*Vh + Wh*Vl + Wl*Vh)
#pragma unroll
        for (int n8 = 0; n8 < 8; n8++) {
#pragma unroll
            for (int kq = 0; kq < 4; kq++) {
                uint32_t bh[4], bl[4];
                uint32_t off = SWZ((kq * 32 + lid) * 128 + n8 * 16);
                ldsm4t(bh, sb + O_VH + off);
                ldsm4t(bl, sb + O_VL + off);
                uint32_t aH0[4] = {wh[4 * kq][0], wh[4 * kq][1], wh[4 * kq + 1][0], wh[4 * kq + 1][1]};
                uint32_t aH1[4] = {wh[4 * kq + 2][0], wh[4 * kq + 2][1], wh[4 * kq + 3][0], wh[4 * kq + 3][1]};
                uint32_t aL0[4] = {wl[4 * kq][0], wl[4 * kq][1], wl[4 * kq + 1][0], wl[4 * kq + 1][1]};
                uint32_t aL1[4] = {wl[4 * kq + 2][0], wl[4 * kq + 2][1], wl[4 * kq + 3][0], wl[4 * kq + 3][1]};
                mma_bf(ctxa[n8], aH0, bh);
                mma_bf(ctxa[n8], aH1, bh + 2);
                mma_bf(ctxa[n8], aL0, bh);
                mma_bf(ctxa[n8], aL1, bh + 2);
                mma_bf(ctxa[n8], aH0, bl);
                mma_bf(ctxa[n8], aH1, bl + 2);
            }
        }
        __syncthreads();
    }

    // ---- ctx store ----
#pragma unroll
    for (int n8 = 0; n8 < 8; n8++) {
        int c = 8 * n8 + 2 * t;
        *(float2*)&ctx[((size_t)nh * S + q0 + r0l) * D + c] = make_float2(ctxa[n8][0], ctxa[n8][1]);
        *(float2*)&ctx[((size_t)nh * S + q0 + r1l) * D + c] = make_float2(ctxa[n8][2], ctxa[n8][3]);
    }
}

// ---------------------------------------------------------------------------
extern "C" void kernel_launch(void* const* d_in, const int* in_sizes, int n_in,
                              void* d_out, int out_size) {
    const float* q = (const float*)d_in[0];
    const float* k = (const float*)d_in[1];
    const float* v = (const float*)d_in[2];
    const int*   m = (const int*)d_in[3];

    float* ctx  = (float*)d_out;
    float* attn = (float*)d_out + CTX_ELEMS;

    cudaFuncSetAttribute(k_attn, cudaFuncAttributeMaxDynamicSharedMemorySize, SMEM_T);

    k_softmax_q<<<dim3(NH, 8), 256>>>(q);
    k_softmax_k<<<(NB * S * D + 255) / 256, 256>>>(k);
    k_pack_mask<<<(S * SW + 255) / 256, 256>>>(m);
    k_attn<<<dim3(16, NH), 256, SMEM_T>>>(v, attn, ctx);
}

// round 7
// speedup vs baseline: 2.7706x; 1.1625x over previous
#include <cuda_runtime.h>
#include <cuda_bf16.h>
#include <cstdint>

#define S 2048
#define D 64
#define NB 2
#define HH 8
#define NH 16
#define SW 64                      /* S/32 mask words per row */
#define CTX_ELEMS (NB*HH*S*D)

// ---------------- scratch (__device__ globals; no allocations) --------------
__device__ __nv_bfloat16 g_Qb[NB*HH*S*D];   // softmaxed Q, bf16
__device__ __nv_bfloat16 g_Kb[NB*HH*S*D];   // softmaxed K, bf16
__device__ __nv_bfloat16 g_Vh[NB*HH*S*D];   // V hi, bf16
__device__ __nv_bfloat16 g_Vl[NB*HH*S*D];   // V residual, bf16
__device__ unsigned      g_mb[S*SW];        // packed mask bits

#define SWZ(o) ((o) ^ (((o) >> 3) & 0x70))

__device__ __forceinline__ uint32_t smem_u32(const void* p) {
    uint32_t a;
    asm("{ .reg .u64 t; cvta.to.shared.u64 t, %1; cvt.u32.u64 %0, t; }" : "=r"(a) : "l"(p));
    return a;
}
__device__ __forceinline__ void ldsm4(uint32_t* r, uint32_t a) {
    asm volatile("ldmatrix.sync.aligned.m8n8.x4.shared.b16 {%0,%1,%2,%3}, [%4];"
                 : "=r"(r[0]), "=r"(r[1]), "=r"(r[2]), "=r"(r[3]) : "r"(a));
}
__device__ __forceinline__ void ldsm4t(uint32_t* r, uint32_t a) {
    asm volatile("ldmatrix.sync.aligned.m8n8.x4.trans.shared.b16 {%0,%1,%2,%3}, [%4];"
                 : "=r"(r[0]), "=r"(r[1]), "=r"(r[2]), "=r"(r[3]) : "r"(a));
}
__device__ __forceinline__ void mma_bf(float* c, const uint32_t* a, const uint32_t* b) {
    asm volatile("mma.sync.aligned.m16n8k16.row.col.f32.bf16.bf16.f32 "
                 "{%0,%1,%2,%3}, {%4,%5,%6,%7}, {%8,%9}, {%0,%1,%2,%3};"
                 : "+f"(c[0]), "+f"(c[1]), "+f"(c[2]), "+f"(c[3])
                 : "r"(a[0]), "r"(a[1]), "r"(a[2]), "r"(a[3]), "r"(b[0]), "r"(b[1]));
}
__device__ __forceinline__ uint32_t pack_bf(__nv_bfloat16 a, __nv_bfloat16 b) {
    __nv_bfloat162 p = __halves2bfloat162(a, b);
    return *(uint32_t*)&p;
}

// ---------------------------------------------------------------------------
// softmax over axis=2 (sequence) for Q -> bf16
// ---------------------------------------------------------------------------
__global__ void k_softmax_q(const float* __restrict__ q) {
    int nh = blockIdx.x, dchunk = blockIdx.y;
    int dloc = threadIdx.x & 7, sy = threadIdx.x >> 3;
    int d = dchunk * 8 + dloc;
    const float* base = q + (size_t)nh * S * D + d;
    float sum = 0.f;
    for (int s = sy; s < S; s += 32) sum += __expf(base[(size_t)s * D]);
    __shared__ float red[32][8];
    red[sy][dloc] = sum;
    __syncthreads();
    for (int off = 16; off > 0; off >>= 1) {
        if (sy < off) red[sy][dloc] += red[sy + off][dloc];
        __syncthreads();
    }
    float iv = 1.f / red[0][dloc];
    __nv_bfloat16* out = g_Qb + (size_t)nh * S * D + d;
    for (int s = sy; s < S; s += 32)
        out[(size_t)s * D] = __float2bfloat16(__expf(base[(size_t)s * D]) * iv);
}

// ---------------------------------------------------------------------------
// softmax over axis=1 (heads) for K -> bf16
// ---------------------------------------------------------------------------
__global__ void k_softmax_k(const float* __restrict__ k) {
    int idx = blockIdx.x * blockDim.x + threadIdx.x;
    if (idx >= NB * S * D) return;
    int n = idx / (S * D);
    int sd = idx - n * (S * D);
    const float* p = k + (size_t)n * HH * S * D + sd;
    __nv_bfloat16* o = g_Kb + (size_t)n * HH * S * D + sd;
    float e[HH]; float sum = 0.f;
#pragma unroll
    for (int h = 0; h < HH; h++) { e[h] = __expf(p[(size_t)h * S * D]); sum += e[h]; }
    float iv = 1.f / sum;
#pragma unroll
    for (int h = 0; h < HH; h++) o[(size_t)h * S * D] = __float2bfloat16(e[h] * iv);
}

// ---------------------------------------------------------------------------
// pack mask bits
// ---------------------------------------------------------------------------
__global__ void k_pack_mask(const int* __restrict__ m) {
    int idx = blockIdx.x * blockDim.x + threadIdx.x;
    if (idx >= S * SW) return;
    int qq = idx >> 6, w = idx & 63;
    const int* p = m + (size_t)qq * S + w * 32;
    unsigned bits = 0;
#pragma unroll
    for (int b = 0; b < 32; b++) if (p[b] != 0) bits |= (1u << b);
    g_mb[idx] = bits;
}

// ---------------------------------------------------------------------------
// V split: g_Vh = bf16(V), g_Vl = bf16(V - f32(g_Vh))
// ---------------------------------------------------------------------------
__global__ void k_vsplit(const float* __restrict__ v) {
    int idx = blockIdx.x * blockDim.x + threadIdx.x;   // over quads
    if (idx >= NB * HH * S * D / 4) return;
    float4 f = *(const float4*)(v + (size_t)idx * 4);
    __nv_bfloat16 h0 = __float2bfloat16(f.x), h1 = __float2bfloat16(f.y);
    __nv_bfloat16 h2 = __float2bfloat16(f.z), h3 = __float2bfloat16(f.w);
    uint32_t vh0 = pack_bf(h0, h1), vh1 = pack_bf(h2, h3);
    __nv_bfloat162 l0 = __floats2bfloat162_rn(f.x - __bfloat162float(h0), f.y - __bfloat162float(h1));
    __nv_bfloat162 l1 = __floats2bfloat162_rn(f.z - __bfloat162float(h2), f.w - __bfloat162float(h3));
    *(uint2*)(g_Vh + (size_t)idx * 4) = make_uint2(vh0, vh1);
    *(uint2*)(g_Vl + (size_t)idx * 4) = make_uint2(*(uint32_t*)&l0, *(uint32_t*)&l1);
}

// ---------------------------------------------------------------------------
// fused attention: per (128-row q-tile, nh)
//   pass1: GEMM1 (HMMA bf16) + masked exp -> row sums
//   pass2: GEMM1 again, chunked epilogue (normalize, store attn fp32,
//          split-bf16 GEMM2 interleaved) -> ctx
// ---------------------------------------------------------------------------
#define O_INVL 0
#define O_MB   512
#define O_Q    3072
#define O_K    (O_Q  + 16384)
#define O_VH   (O_K  + 16384)
#define O_VL   (O_VH + 16384)
#define SMEM_T (O_VL + 16384)   /* 68608 bytes */

__global__ void __launch_bounds__(256, 2) k_attn(float* __restrict__ attn,
                                                 float* __restrict__ ctx) {
    extern __shared__ char smem[];
    const int tid = threadIdx.x, wid = tid >> 5, lid = tid & 31;
    const int g = lid >> 2, t = lid & 3;
    const int nh = blockIdx.y, q0 = blockIdx.x * 128;
    const uint32_t sb = smem_u32(smem);
    float* invl = (float*)(smem + O_INVL);

    const __nv_bfloat16* Qg  = g_Qb + ((size_t)nh * S + q0) * D;
    const __nv_bfloat16* Kg  = g_Kb + (size_t)nh * S * D;
    const __nv_bfloat16* Vhg = g_Vh + (size_t)nh * S * D;
    const __nv_bfloat16* Vlg = g_Vl + (size_t)nh * S * D;
    float* attnb = attn + (size_t)nh * S * S;

    // ---- load Q tile (128x64 bf16, SW128-swizzled rows of 128B) ----
#pragma unroll
    for (int i = 0; i < 4; i++) {
        int idx = i * 256 + tid;
        int r = idx >> 3, s16 = idx & 7;
        *(uint4*)(smem + O_Q + SWZ(r * 128 + s16 * 16)) =
            *(const uint4*)(Qg + (size_t)r * 64 + s16 * 8);
    }
    __syncthreads();

    // hoist A fragments (rows 16*wid..+15, 4 k16 steps)
    uint32_t aQ[4][4];
#pragma unroll
    for (int kk = 0; kk < 4; kk++) {
        int rl = 16 * wid + (lid & 7) + (lid & 8);
        int c16 = kk * 2 + (lid >> 4);
        ldsm4(aQ[kk], sb + O_Q + SWZ(rl * 128 + c16 * 16));
    }

    const int r0l = 16 * wid + g, r1l = r0l + 8;

    // ================= pass 1: row sums =================
    float rs0 = 0.f, rs1 = 0.f;
    for (int kt = 0; kt < 16; kt++) {
#pragma unroll
        for (int i = 0; i < 4; i++) {
            int idx = i * 256 + tid;
            int r = idx >> 3, s16 = idx & 7;
            *(uint4*)(smem + O_K + SWZ(r * 128 + s16 * 16)) =
                *(const uint4*)(Kg + (size_t)(kt * 128 + r) * 64 + s16 * 8);
        }
        if (tid < 128)
            *(uint4*)(smem + O_MB + tid * 16) =
                *(const uint4*)(g_mb + (size_t)(q0 + tid) * SW + kt * 4);
        __syncthreads();

        uint4 mw0 = *(uint4*)(smem + O_MB + r0l * 16);
        uint4 mw1 = *(uint4*)(smem + O_MB + r1l * 16);
        unsigned m0a[4] = {mw0.x, mw0.y, mw0.z, mw0.w};
        unsigned m1a[4] = {mw1.x, mw1.y, mw1.z, mw1.w};

#pragma unroll
        for (int c = 0; c < 4; c++) {
            float acc4[4][4];
#pragma unroll
            for (int f4 = 0; f4 < 4; f4++) { acc4[f4][0] = acc4[f4][1] = acc4[f4][2] = acc4[f4][3] = 0.f; }
#pragma unroll
            for (int f4 = 0; f4 < 4; f4++) {
                int f = 4 * c + f4;
#pragma unroll
                for (int kp = 0; kp < 2; kp++) {
                    uint32_t b[4];
                    ldsm4(b, sb + O_K + SWZ((f * 8 + (lid & 7)) * 128 + (kp * 4 + (lid >> 3)) * 16));
                    mma_bf(acc4[f4], aQ[2 * kp], b);
                    mma_bf(acc4[f4], aQ[2 * kp + 1], b + 2);
                }
            }
            unsigned w0 = m0a[c], w1 = m1a[c];
#pragma unroll
            for (int f4 = 0; f4 < 4; f4++) {
                int bit = 8 * f4 + 2 * t;
                if ((w0 >> bit) & 1)       rs0 += __expf(acc4[f4][0]);
                if ((w0 >> (bit + 1)) & 1) rs0 += __expf(acc4[f4][1]);
                if ((w1 >> bit) & 1)       rs1 += __expf(acc4[f4][2]);
                if ((w1 >> (bit + 1)) & 1) rs1 += __expf(acc4[f4][3]);
            }
        }
        __syncthreads();
    }
    rs0 += __shfl_xor_sync(0xffffffffu, rs0, 1);
    rs0 += __shfl_xor_sync(0xffffffffu, rs0, 2);
    rs1 += __shfl_xor_sync(0xffffffffu, rs1, 1);
    rs1 += __shfl_xor_sync(0xffffffffu, rs1, 2);
    if (t == 0) {
        invl[r0l] = rs0 > 0.f ? 1.f / rs0 : 0.f;
        invl[r1l] = rs1 > 0.f ? 1.f / rs1 : 0.f;
    }
    __syncthreads();
    const float iv0 = invl[r0l], iv1 = invl[r1l];

    // ================= pass 2: recompute + normalize + chunked GEMM2 ========
    float ctxa[8][4];
#pragma unroll
    for (int n = 0; n < 8; n++) { ctxa[n][0] = ctxa[n][1] = ctxa[n][2] = ctxa[n][3] = 0.f; }

    for (int kt = 0; kt < 16; kt++) {
#pragma unroll
        for (int i = 0; i < 4; i++) {
            int idx = i * 256 + tid;
            int r = idx >> 3, s16 = idx & 7;
            uint32_t swo = SWZ(r * 128 + s16 * 16);
            const size_t gofs = (size_t)(kt * 128 + r) * 64 + s16 * 8;
            *(uint4*)(smem + O_K  + swo) = *(const uint4*)(Kg  + gofs);
            *(uint4*)(smem + O_VH + swo) = *(const uint4*)(Vhg + gofs);
            *(uint4*)(smem + O_VL + swo) = *(const uint4*)(Vlg + gofs);
        }
        if (tid < 128)
            *(uint4*)(smem + O_MB + tid * 16) =
                *(const uint4*)(g_mb + (size_t)(q0 + tid) * SW + kt * 4);
        __syncthreads();

        uint4 mw0 = *(uint4*)(smem + O_MB + r0l * 16);
        uint4 mw1 = *(uint4*)(smem + O_MB + r1l * 16);
        unsigned m0a[4] = {mw0.x, mw0.y, mw0.z, mw0.w};
        unsigned m1a[4] = {mw1.x, mw1.y, mw1.z, mw1.w};

#pragma unroll
        for (int c = 0; c < 4; c++) {
            // --- GEMM1 for 4 fragments (32 attn cols) ---
            float acc4[4][4];
#pragma unroll
            for (int f4 = 0; f4 < 4; f4++) { acc4[f4][0] = acc4[f4][1] = acc4[f4][2] = acc4[f4][3] = 0.f; }
#pragma unroll
            for (int f4 = 0; f4 < 4; f4++) {
                int f = 4 * c + f4;
#pragma unroll
                for (int kp = 0; kp < 2; kp++) {
                    uint32_t b[4];
                    ldsm4(b, sb + O_K + SWZ((f * 8 + (lid & 7)) * 128 + (kp * 4 + (lid >> 3)) * 16));
                    mma_bf(acc4[f4], aQ[2 * kp], b);
                    mma_bf(acc4[f4], aQ[2 * kp + 1], b + 2);
                }
            }
            // --- epilogue: masked exp, normalize, store, split W frags ---
            unsigned w0 = m0a[c], w1 = m1a[c];
            uint32_t wh4[4][2], wl4[4][2];
#pragma unroll
            for (int f4 = 0; f4 < 4; f4++) {
                int bit = 8 * f4 + 2 * t;
                float e0 = ((w0 >> bit) & 1)       ? __expf(acc4[f4][0]) * iv0 : 0.f;
                float e1 = ((w0 >> (bit + 1)) & 1) ? __expf(acc4[f4][1]) * iv0 : 0.f;
                float e2 = ((w1 >> bit) & 1)       ? __expf(acc4[f4][2]) * iv1 : 0.f;
                float e3 = ((w1 >> (bit + 1)) & 1) ? __expf(acc4[f4][3]) * iv1 : 0.f;
                int col = kt * 128 + 32 * c + 8 * f4 + 2 * t;
                *(float2*)&attnb[(size_t)(q0 + r0l) * S + col] = make_float2(e0, e1);
                *(float2*)&attnb[(size_t)(q0 + r1l) * S + col] = make_float2(e2, e3);
                __nv_bfloat16 h0 = __float2bfloat16(e0), h1 = __float2bfloat16(e1);
                __nv_bfloat16 h2 = __float2bfloat16(e2), h3 = __float2bfloat16(e3);
                wh4[f4][0] = pack_bf(h0, h1);
                wh4[f4][1] = pack_bf(h2, h3);
                __nv_bfloat162 l01 = __floats2bfloat162_rn(e0 - __bfloat162float(h0),
                                                           e1 - __bfloat162float(h1));
                __nv_bfloat162 l23 = __floats2bfloat162_rn(e2 - __bfloat162float(h2),
                                                           e3 - __bfloat162float(h3));
                wl4[f4][0] = *(uint32_t*)&l01;
                wl4[f4][1] = *(uint32_t*)&l23;
            }
            // --- GEMM2 partial: ctx += W[:,32c..32c+31] @ V[32c..32c+31,:] ---
            uint32_t aH0[4] = {wh4[0][0], wh4[0][1], wh4[1][0], wh4[1][1]};
            uint32_t aH1[4] = {wh4[2][0], wh4[2][1], wh4[3][0], wh4[3][1]};
            uint32_t aL0[4] = {wl4[0][0], wl4[0][1], wl4[1][0], wl4[1][1]};
            uint32_t aL1[4] = {wl4[2][0], wl4[2][1], wl4[3][0], wl4[3][1]};
#pragma unroll
            for (int n8 = 0; n8 < 8; n8++) {
                uint32_t bh[4], bl[4];
                uint32_t off = SWZ((c * 32 + lid) * 128 + n8 * 16);
                ldsm4t(bh, sb + O_VH + off);
                ldsm4t(bl, sb + O_VL + off);
                mma_bf(ctxa[n8], aH0, bh);
                mma_bf(ctxa[n8], aH1, bh + 2);
                mma_bf(ctxa[n8], aL0, bh);
                mma_bf(ctxa[n8], aL1, bh + 2);
                mma_bf(ctxa[n8], aH0, bl);
                mma_bf(ctxa[n8], aH1, bl + 2);
            }
        }
        __syncthreads();
    }

    // ---- ctx store ----
#pragma unroll
    for (int n8 = 0; n8 < 8; n8++) {
        int c = 8 * n8 + 2 * t;
        *(float2*)&ctx[((size_t)nh * S + q0 + r0l) * D + c] = make_float2(ctxa[n8][0], ctxa[n8][1]);
        *(float2*)&ctx[((size_t)nh * S + q0 + r1l) * D + c] = make_float2(ctxa[n8][2], ctxa[n8][3]);
    }
}

// ---------------------------------------------------------------------------
extern "C" void kernel_launch(void* const* d_in, const int* in_sizes, int n_in,
                              void* d_out, int out_size) {
    const float* q = (const float*)d_in[0];
    const float* k = (const float*)d_in[1];
    const float* v = (const float*)d_in[2];
    const int*   m = (const int*)d_in[3];

    float* ctx  = (float*)d_out;
    float* attn = (float*)d_out + CTX_ELEMS;

    cudaFuncSetAttribute(k_attn, cudaFuncAttributeMaxDynamicSharedMemorySize, SMEM_T);

    k_softmax_q<<<dim3(NH, 8), 256>>>(q);
    k_softmax_k<<<(NB * S * D + 255) / 256, 256>>>(k);
    k_pack_mask<<<(S * SW + 255) / 256, 256>>>(m);
    k_vsplit<<<(NB * HH * S * D / 4 + 255) / 256, 256>>>(v);
    k_attn<<<dim3(16, NH), 256, SMEM_T>>>(attn, ctx);
}

// round 9
// speedup vs baseline: 3.0591x; 1.1041x over previous
#include <cuda_runtime.h>
#include <cuda_bf16.h>
#include <cstdint>

#define S 2048
#define D 64
#define NB 2
#define HH 8
#define NH 16
#define SW 64                      /* S/32 mask words per row */
#define CTX_ELEMS (NB*HH*S*D)

// ---------------- scratch (__device__ globals; no allocations) --------------
__device__ __nv_bfloat16 g_Qb[NB*HH*S*D];   // softmaxed Q, bf16
__device__ __nv_bfloat16 g_Kb[NB*HH*S*D];   // softmaxed K, bf16
__device__ __nv_bfloat16 g_Vh[NB*HH*S*D];   // V hi, bf16
__device__ __nv_bfloat16 g_Vl[NB*HH*S*D];   // V residual, bf16
__device__ unsigned      g_mb[S*SW];        // packed mask bits

#define SWZ(o) ((o) ^ (((o) >> 3) & 0x70))

__device__ __forceinline__ uint32_t smem_u32(const void* p) {
    uint32_t a;
    asm("{ .reg .u64 t; cvta.to.shared.u64 t, %1; cvt.u32.u64 %0, t; }" : "=r"(a) : "l"(p));
    return a;
}
__device__ __forceinline__ void cpa16(uint32_t dst, const void* src) {
    asm volatile("cp.async.cg.shared.global [%0], [%1], 16;"
                 :: "r"(dst), "l"(__cvta_generic_to_global(src)) : "memory");
}
#define CPA_COMMIT() asm volatile("cp.async.commit_group;" ::: "memory")
#define CPA_WAIT0()  asm volatile("cp.async.wait_group 0;" ::: "memory")

__device__ __forceinline__ void ldsm4(uint32_t* r, uint32_t a) {
    asm volatile("ldmatrix.sync.aligned.m8n8.x4.shared.b16 {%0,%1,%2,%3}, [%4];"
                 : "=r"(r[0]), "=r"(r[1]), "=r"(r[2]), "=r"(r[3]) : "r"(a));
}
__device__ __forceinline__ void ldsm4t(uint32_t* r, uint32_t a) {
    asm volatile("ldmatrix.sync.aligned.m8n8.x4.trans.shared.b16 {%0,%1,%2,%3}, [%4];"
                 : "=r"(r[0]), "=r"(r[1]), "=r"(r[2]), "=r"(r[3]) : "r"(a));
}
__device__ __forceinline__ void mma_bf(float* c, const uint32_t* a, const uint32_t* b) {
    asm volatile("mma.sync.aligned.m16n8k16.row.col.f32.bf16.bf16.f32 "
                 "{%0,%1,%2,%3}, {%4,%5,%6,%7}, {%8,%9}, {%0,%1,%2,%3};"
                 : "+f"(c[0]), "+f"(c[1]), "+f"(c[2]), "+f"(c[3])
                 : "r"(a[0]), "r"(a[1]), "r"(a[2]), "r"(a[3]), "r"(b[0]), "r"(b[1]));
}
__device__ __forceinline__ uint32_t pack_bf(__nv_bfloat16 a, __nv_bfloat16 b) {
    __nv_bfloat162 p = __halves2bfloat162(a, b);
    return *(uint32_t*)&p;
}

// ---------------------------------------------------------------------------
// softmax over axis=2 (sequence) for Q -> bf16
// ---------------------------------------------------------------------------
__global__ void k_softmax_q(const float* __restrict__ q) {
    int nh = blockIdx.x, dchunk = blockIdx.y;
    int dloc = threadIdx.x & 7, sy = threadIdx.x >> 3;
    int d = dchunk * 8 + dloc;
    const float* base = q + (size_t)nh * S * D + d;
    float sum = 0.f;
    for (int s = sy; s < S; s += 32) sum += __expf(base[(size_t)s * D]);
    __shared__ float red[32][8];
    red[sy][dloc] = sum;
    __syncthreads();
    for (int off = 16; off > 0; off >>= 1) {
        if (sy < off) red[sy][dloc] += red[sy + off][dloc];
        __syncthreads();
    }
    float iv = 1.f / red[0][dloc];
    __nv_bfloat16* out = g_Qb + (size_t)nh * S * D + d;
    for (int s = sy; s < S; s += 32)
        out[(size_t)s * D] = __float2bfloat16(__expf(base[(size_t)s * D]) * iv);
}

// ---------------------------------------------------------------------------
// softmax over axis=1 (heads) for K -> bf16
// ---------------------------------------------------------------------------
__global__ void k_softmax_k(const float* __restrict__ k) {
    int idx = blockIdx.x * blockDim.x + threadIdx.x;
    if (idx >= NB * S * D) return;
    int n = idx / (S * D);
    int sd = idx - n * (S * D);
    const float* p = k + (size_t)n * HH * S * D + sd;
    __nv_bfloat16* o = g_Kb + (size_t)n * HH * S * D + sd;
    float e[HH]; float sum = 0.f;
#pragma unroll
    for (int h = 0; h < HH; h++) { e[h] = __expf(p[(size_t)h * S * D]); sum += e[h]; }
    float iv = 1.f / sum;
#pragma unroll
    for (int h = 0; h < HH; h++) o[(size_t)h * S * D] = __float2bfloat16(e[h] * iv);
}

// ---------------------------------------------------------------------------
// pack mask bits
// ---------------------------------------------------------------------------
__global__ void k_pack_mask(const int* __restrict__ m) {
    int idx = blockIdx.x * blockDim.x + threadIdx.x;
    if (idx >= S * SW) return;
    int qq = idx >> 6, w = idx & 63;
    const int* p = m + (size_t)qq * S + w * 32;
    unsigned bits = 0;
#pragma unroll
    for (int b = 0; b < 32; b++) if (p[b] != 0) bits |= (1u << b);
    g_mb[idx] = bits;
}

// ---------------------------------------------------------------------------
// V split: g_Vh = bf16(V), g_Vl = bf16(V - f32(g_Vh))
// ---------------------------------------------------------------------------
__global__ void k_vsplit(const float* __restrict__ v) {
    int idx = blockIdx.x * blockDim.x + threadIdx.x;   // over quads
    if (idx >= NB * HH * S * D / 4) return;
    float4 f = *(const float4*)(v + (size_t)idx * 4);
    __nv_bfloat16 h0 = __float2bfloat16(f.x), h1 = __float2bfloat16(f.y);
    __nv_bfloat16 h2 = __float2bfloat16(f.z), h3 = __float2bfloat16(f.w);
    uint32_t vh0 = pack_bf(h0, h1), vh1 = pack_bf(h2, h3);
    __nv_bfloat162 l0 = __floats2bfloat162_rn(f.x - __bfloat162float(h0), f.y - __bfloat162float(h1));
    __nv_bfloat162 l1 = __floats2bfloat162_rn(f.z - __bfloat162float(h2), f.w - __bfloat162float(h3));
    *(uint2*)(g_Vh + (size_t)idx * 4) = make_uint2(vh0, vh1);
    *(uint2*)(g_Vl + (size_t)idx * 4) = make_uint2(*(uint32_t*)&l0, *(uint32_t*)&l1);
}

// ---------------------------------------------------------------------------
// fused attention, cp.async double-buffered
// smem layout (bytes):
// ---------------------------------------------------------------------------
#define O_INVL 0
#define O_MB0  512
#define O_MB1  2560
#define O_KB0  4608
#define O_KB1  20992    /* also Q tile during prologue */
#define O_VH0  37376
#define O_VH1  53760
#define O_VL0  70144
#define O_VL1  86528
#define SMEM_T 102912

__global__ void __launch_bounds__(256, 2) k_attn(float* __restrict__ attn,
                                                 float* __restrict__ ctx) {
    extern __shared__ char smem[];
    const int tid = threadIdx.x, wid = tid >> 5, lid = tid & 31;
    const int g = lid >> 2, t = lid & 3;
    const int nh = blockIdx.y, q0 = blockIdx.x * 128;
    const uint32_t sb = smem_u32(smem);
    float* invl = (float*)(smem + O_INVL);

    const __nv_bfloat16* Qg  = g_Qb + ((size_t)nh * S + q0) * D;
    const __nv_bfloat16* Kg  = g_Kb + (size_t)nh * S * D;
    const __nv_bfloat16* Vhg = g_Vh + (size_t)nh * S * D;
    const __nv_bfloat16* Vlg = g_Vl + (size_t)nh * S * D;
    float* attnb = attn + (size_t)nh * S * S;

    // ---- prefetch K tile 0 + mask 0 into buf 0 (overlaps Q load/hoist) ----
    {
#pragma unroll
        for (int i = 0; i < 4; i++) {
            int idx = i * 256 + tid;
            int r = idx >> 3, s16 = idx & 7;
            cpa16(sb + O_KB0 + SWZ(r * 128 + s16 * 16), Kg + (size_t)r * 64 + s16 * 8);
        }
        if (tid < 128)
            cpa16(sb + O_MB0 + tid * 16, g_mb + (size_t)(q0 + tid) * SW);
        CPA_COMMIT();
    }

    // ---- load Q tile into KB1 region, hoist fragments, then recycle ----
#pragma unroll
    for (int i = 0; i < 4; i++) {
        int idx = i * 256 + tid;
        int r = idx >> 3, s16 = idx & 7;
        *(uint4*)(smem + O_KB1 + SWZ(r * 128 + s16 * 16)) =
            *(const uint4*)(Qg + (size_t)r * 64 + s16 * 8);
    }
    __syncthreads();
    uint32_t aQ[4][4];
#pragma unroll
    for (int kk = 0; kk < 4; kk++) {
        int rl = 16 * wid + (lid & 7) + (lid & 8);
        int c16 = kk * 2 + (lid >> 4);
        ldsm4(aQ[kk], sb + O_KB1 + SWZ(rl * 128 + c16 * 16));
    }
    __syncthreads();   // Q region now reusable as K buffer 1

    const int r0l = 16 * wid + g, r1l = r0l + 8;

    // ================= pass 1: row sums =================
    float rs0 = 0.f, rs1 = 0.f;
    for (int kt = 0; kt < 16; kt++) {
        CPA_WAIT0();
        __syncthreads();
        if (kt < 15) {   // prefetch kt+1
            int b = (kt + 1) & 1;
            uint32_t kb = b ? O_KB1 : O_KB0, mb = b ? O_MB1 : O_MB0;
#pragma unroll
            for (int i = 0; i < 4; i++) {
                int idx = i * 256 + tid;
                int r = idx >> 3, s16 = idx & 7;
                cpa16(sb + kb + SWZ(r * 128 + s16 * 16),
                      Kg + (size_t)((kt + 1) * 128 + r) * 64 + s16 * 8);
            }
            if (tid < 128)
                cpa16(sb + mb + tid * 16, g_mb + (size_t)(q0 + tid) * SW + (kt + 1) * 4);
            CPA_COMMIT();
        }
        const uint32_t kb = (kt & 1) ? O_KB1 : O_KB0;
        const uint32_t mb = (kt & 1) ? O_MB1 : O_MB0;

        uint4 mw0 = *(uint4*)(smem + mb + r0l * 16);
        uint4 mw1 = *(uint4*)(smem + mb + r1l * 16);
        unsigned m0a[4] = {mw0.x, mw0.y, mw0.z, mw0.w};
        unsigned m1a[4] = {mw1.x, mw1.y, mw1.z, mw1.w};

#pragma unroll
        for (int c = 0; c < 4; c++) {
            float acc4[4][4];
#pragma unroll
            for (int f4 = 0; f4 < 4; f4++) { acc4[f4][0] = acc4[f4][1] = acc4[f4][2] = acc4[f4][3] = 0.f; }
#pragma unroll
            for (int f4 = 0; f4 < 4; f4++) {
                int f = 4 * c + f4;
#pragma unroll
                for (int kp = 0; kp < 2; kp++) {
                    uint32_t b[4];
                    ldsm4(b, sb + kb + SWZ((f * 8 + (lid & 7)) * 128 + (kp * 4 + (lid >> 3)) * 16));
                    mma_bf(acc4[f4], aQ[2 * kp], b);
                    mma_bf(acc4[f4], aQ[2 * kp + 1], b + 2);
                }
            }
            unsigned w0 = m0a[c], w1 = m1a[c];
#pragma unroll
            for (int f4 = 0; f4 < 4; f4++) {
                int bit = 8 * f4 + 2 * t;
                if ((w0 >> bit) & 1)       rs0 += __expf(acc4[f4][0]);
                if ((w0 >> (bit + 1)) & 1) rs0 += __expf(acc4[f4][1]);
                if ((w1 >> bit) & 1)       rs1 += __expf(acc4[f4][2]);
                if ((w1 >> (bit + 1)) & 1) rs1 += __expf(acc4[f4][3]);
            }
        }
    }

    // ---- prefetch pass-2 tile 0 early (overlaps reduction) ----
    {
#pragma unroll
        for (int i = 0; i < 4; i++) {
            int idx = i * 256 + tid;
            int r = idx >> 3, s16 = idx & 7;
            uint32_t swo = SWZ(r * 128 + s16 * 16);
            size_t gofs = (size_t)r * 64 + s16 * 8;
            cpa16(sb + O_KB0 + swo, Kg  + gofs);
            cpa16(sb + O_VH0 + swo, Vhg + gofs);
            cpa16(sb + O_VL0 + swo, Vlg + gofs);
        }
        if (tid < 128)
            cpa16(sb + O_MB0 + tid * 16, g_mb + (size_t)(q0 + tid) * SW);
        CPA_COMMIT();
    }

    rs0 += __shfl_xor_sync(0xffffffffu, rs0, 1);
    rs0 += __shfl_xor_sync(0xffffffffu, rs0, 2);
    rs1 += __shfl_xor_sync(0xffffffffu, rs1, 1);
    rs1 += __shfl_xor_sync(0xffffffffu, rs1, 2);
    if (t == 0) {
        invl[r0l] = rs0 > 0.f ? 1.f / rs0 : 0.f;
        invl[r1l] = rs1 > 0.f ? 1.f / rs1 : 0.f;
    }
    __syncthreads();
    const float iv0 = invl[r0l], iv1 = invl[r1l];

    // ================= pass 2: recompute + normalize + chunked GEMM2 ========
    float ctxa[8][4];
#pragma unroll
    for (int n = 0; n < 8; n++) { ctxa[n][0] = ctxa[n][1] = ctxa[n][2] = ctxa[n][3] = 0.f; }

    for (int kt = 0; kt < 16; kt++) {
        CPA_WAIT0();
        __syncthreads();
        if (kt < 15) {   // prefetch kt+1
            int b = (kt + 1) & 1;
            uint32_t kb = b ? O_KB1 : O_KB0, vh = b ? O_VH1 : O_VH0;
            uint32_t vl = b ? O_VL1 : O_VL0, mb = b ? O_MB1 : O_MB0;
#pragma unroll
            for (int i = 0; i < 4; i++) {
                int idx = i * 256 + tid;
                int r = idx >> 3, s16 = idx & 7;
                uint32_t swo = SWZ(r * 128 + s16 * 16);
                size_t gofs = (size_t)((kt + 1) * 128 + r) * 64 + s16 * 8;
                cpa16(sb + kb + swo, Kg  + gofs);
                cpa16(sb + vh + swo, Vhg + gofs);
                cpa16(sb + vl + swo, Vlg + gofs);
            }
            if (tid < 128)
                cpa16(sb + mb + tid * 16, g_mb + (size_t)(q0 + tid) * SW + (kt + 1) * 4);
            CPA_COMMIT();
        }
        const int bsel = kt & 1;
        const uint32_t kb  = bsel ? O_KB1 : O_KB0;
        const uint32_t vhb = bsel ? O_VH1 : O_VH0;
        const uint32_t vlb = bsel ? O_VL1 : O_VL0;
        const uint32_t mb  = bsel ? O_MB1 : O_MB0;

        uint4 mw0 = *(uint4*)(smem + mb + r0l * 16);
        uint4 mw1 = *(uint4*)(smem + mb + r1l * 16);
        unsigned m0a[4] = {mw0.x, mw0.y, mw0.z, mw0.w};
        unsigned m1a[4] = {mw1.x, mw1.y, mw1.z, mw1.w};

#pragma unroll
        for (int c = 0; c < 4; c++) {
            // --- GEMM1 for 4 fragments (32 attn cols) ---
            float acc4[4][4];
#pragma unroll
            for (int f4 = 0; f4 < 4; f4++) { acc4[f4][0] = acc4[f4][1] = acc4[f4][2] = acc4[f4][3] = 0.f; }
#pragma unroll
            for (int f4 = 0; f4 < 4; f4++) {
                int f = 4 * c + f4;
#pragma unroll
                for (int kp = 0; kp < 2; kp++) {
                    uint32_t b[4];
                    ldsm4(b, sb + kb + SWZ((f * 8 + (lid & 7)) * 128 + (kp * 4 + (lid >> 3)) * 16));
                    mma_bf(acc4[f4], aQ[2 * kp], b);
                    mma_bf(acc4[f4], aQ[2 * kp + 1], b + 2);
                }
            }
            // --- epilogue: masked exp, normalize, store, split W frags ---
            unsigned w0 = m0a[c], w1 = m1a[c];
            uint32_t wh4[4][2], wl4[4][2];
#pragma unroll
            for (int f4 = 0; f4 < 4; f4++) {
                int bit = 8 * f4 + 2 * t;
                float e0 = ((w0 >> bit) & 1)       ? __expf(acc4[f4][0]) * iv0 : 0.f;
                float e1 = ((w0 >> (bit + 1)) & 1) ? __expf(acc4[f4][1]) * iv0 : 0.f;
                float e2 = ((w1 >> bit) & 1)       ? __expf(acc4[f4][2]) * iv1 : 0.f;
                float e3 = ((w1 >> (bit + 1)) & 1) ? __expf(acc4[f4][3]) * iv1 : 0.f;
                int col = kt * 128 + 32 * c + 8 * f4 + 2 * t;
                *(float2*)&attnb[(size_t)(q0 + r0l) * S + col] = make_float2(e0, e1);
                *(float2*)&attnb[(size_t)(q0 + r1l) * S + col] = make_float2(e2, e3);
                __nv_bfloat16 h0 = __float2bfloat16(e0), h1 = __float2bfloat16(e1);
                __nv_bfloat16 h2 = __float2bfloat16(e2), h3 = __float2bfloat16(e3);
                wh4[f4][0] = pack_bf(h0, h1);
                wh4[f4][1] = pack_bf(h2, h3);
                __nv_bfloat162 l01 = __floats2bfloat162_rn(e0 - __bfloat162float(h0),
                                                           e1 - __bfloat162float(h1));
                __nv_bfloat162 l23 = __floats2bfloat162_rn(e2 - __bfloat162float(h2),
                                                           e3 - __bfloat162float(h3));
                wl4[f4][0] = *(uint32_t*)&l01;
                wl4[f4][1] = *(uint32_t*)&l23;
            }
            // --- GEMM2 partial: ctx += W[:,32c..32c+31] @ V[32c..32c+31,:] ---
            uint32_t aH0[4] = {wh4[0][0], wh4[0][1], wh4[1][0], wh4[1][1]};
            uint32_t aH1[4] = {wh4[2][0], wh4[2][1], wh4[3][0], wh4[3][1]};
            uint32_t aL0[4] = {wl4[0][0], wl4[0][1], wl4[1][0], wl4[1][1]};
            uint32_t aL1[4] = {wl4[2][0], wl4[2][1], wl4[3][0], wl4[3][1]};
#pragma unroll
            for (int n8 = 0; n8 < 8; n8++) {
                uint32_t bh[4], bl[4];
                uint32_t off = SWZ((c * 32 + lid) * 128 + n8 * 16);
                ldsm4t(bh, sb + vhb + off);
                ldsm4t(bl, sb + vlb + off);
                mma_bf(ctxa[n8], aH0, bh);
                mma_bf(ctxa[n8], aH1, bh + 2);
                mma_bf(ctxa[n8], aL0, bh);
                mma_bf(ctxa[n8], aL1, bh + 2);
                mma_bf(ctxa[n8], aH0, bl);
                mma_bf(ctxa[n8], aH1, bl + 2);
            }
        }
    }

    // ---- ctx store ----
#pragma unroll
    for (int n8 = 0; n8 < 8; n8++) {
        int c = 8 * n8 + 2 * t;
        *(float2*)&ctx[((size_t)nh * S + q0 + r0l) * D + c] = make_float2(ctxa[n8][0], ctxa[n8][1]);
        *(float2*)&ctx[((size_t)nh * S + q0 + r1l) * D + c] = make_float2(ctxa[n8][2], ctxa[n8][3]);
    }
}

// ---------------------------------------------------------------------------
extern "C" void kernel_launch(void* const* d_in, const int* in_sizes, int n_in,
                              void* d_out, int out_size) {
    const float* q = (const float*)d_in[0];
    const float* k = (const float*)d_in[1];
    const float* v = (const float*)d_in[2];
    const int*   m = (const int*)d_in[3];

    float* ctx  = (float*)d_out;
    float* attn = (float*)d_out + CTX_ELEMS;

    cudaFuncSetAttribute(k_attn, cudaFuncAttributeMaxDynamicSharedMemorySize, SMEM_T);

    k_softmax_q<<<dim3(NH, 8), 256>>>(q);
    k_softmax_k<<<(NB * S * D + 255) / 256, 256>>>(k);
    k_pack_mask<<<(S * SW + 255) / 256, 256>>>(m);
    k_vsplit<<<(NB * HH * S * D / 4 + 255) / 256, 256>>>(v);
    k_attn<<<dim3(16, NH), 256, SMEM_T>>>(attn, ctx);
}

// round 10
// speedup vs baseline: 3.5403x; 1.1573x over previous
#include <cuda_runtime.h>
#include <cuda_fp16.h>
#include <cstdint>

#define S 2048
#define D 64
#define NB 2
#define HH 8
#define NH 16
#define SW 64                      /* S/32 mask words per row */
#define CTX_ELEMS (NB*HH*S*D)

// ---------------- scratch (__device__ globals; no allocations) --------------
__device__ __half    g_Qh[NB*HH*S*D];   // softmaxed Q, fp16
__device__ __half    g_Kh[NB*HH*S*D];   // softmaxed K, fp16
__device__ __half    g_Vf[NB*HH*S*D];   // V, fp16
__device__ unsigned  g_mb[S*SW];        // packed mask bits

#define SWZ(o) ((o) ^ (((o) >> 3) & 0x70))

__device__ __forceinline__ uint32_t smem_u32(const void* p) {
    uint32_t a;
    asm("{ .reg .u64 t; cvta.to.shared.u64 t, %1; cvt.u32.u64 %0, t; }" : "=r"(a) : "l"(p));
    return a;
}
__device__ __forceinline__ void cpa16(uint32_t dst, const void* src) {
    asm volatile("cp.async.cg.shared.global [%0], [%1], 16;"
                 :: "r"(dst), "l"(__cvta_generic_to_global(src)) : "memory");
}
#define CPA_COMMIT() asm volatile("cp.async.commit_group;" ::: "memory")
#define CPA_WAIT0()  asm volatile("cp.async.wait_group 0;" ::: "memory")

__device__ __forceinline__ void ldsm4(uint32_t* r, uint32_t a) {
    asm volatile("ldmatrix.sync.aligned.m8n8.x4.shared.b16 {%0,%1,%2,%3}, [%4];"
                 : "=r"(r[0]), "=r"(r[1]), "=r"(r[2]), "=r"(r[3]) : "r"(a));
}
__device__ __forceinline__ void ldsm4t(uint32_t* r, uint32_t a) {
    asm volatile("ldmatrix.sync.aligned.m8n8.x4.trans.shared.b16 {%0,%1,%2,%3}, [%4];"
                 : "=r"(r[0]), "=r"(r[1]), "=r"(r[2]), "=r"(r[3]) : "r"(a));
}
__device__ __forceinline__ void mma_fp(float* c, const uint32_t* a, const uint32_t* b) {
    asm volatile("mma.sync.aligned.m16n8k16.row.col.f32.f16.f16.f32 "
                 "{%0,%1,%2,%3}, {%4,%5,%6,%7}, {%8,%9}, {%0,%1,%2,%3};"
                 : "+f"(c[0]), "+f"(c[1]), "+f"(c[2]), "+f"(c[3])
                 : "r"(a[0]), "r"(a[1]), "r"(a[2]), "r"(a[3]), "r"(b[0]), "r"(b[1]));
}
__device__ __forceinline__ uint32_t pack_h(__half a, __half b) {
    __half2 p = __halves2half2(a, b);
    return *(uint32_t*)&p;
}

// ---------------------------------------------------------------------------
// softmax over axis=2 (sequence) for Q -> fp16
// ---------------------------------------------------------------------------
__global__ void k_softmax_q(const float* __restrict__ q) {
    int nh = blockIdx.x, dchunk = blockIdx.y;
    int dloc = threadIdx.x & 7, sy = threadIdx.x >> 3;
    int d = dchunk * 8 + dloc;
    const float* base = q + (size_t)nh * S * D + d;
    float sum = 0.f;
    for (int s = sy; s < S; s += 32) sum += __expf(base[(size_t)s * D]);
    __shared__ float red[32][8];
    red[sy][dloc] = sum;
    __syncthreads();
    for (int off = 16; off > 0; off >>= 1) {
        if (sy < off) red[sy][dloc] += red[sy + off][dloc];
        __syncthreads();
    }
    float iv = 1.f / red[0][dloc];
    __half* out = g_Qh + (size_t)nh * S * D + d;
    for (int s = sy; s < S; s += 32)
        out[(size_t)s * D] = __float2half_rn(__expf(base[(size_t)s * D]) * iv);
}

// ---------------------------------------------------------------------------
// softmax over axis=1 (heads) for K -> fp16
// ---------------------------------------------------------------------------
__global__ void k_softmax_k(const float* __restrict__ k) {
    int idx = blockIdx.x * blockDim.x + threadIdx.x;
    if (idx >= NB * S * D) return;
    int n = idx / (S * D);
    int sd = idx - n * (S * D);
    const float* p = k + (size_t)n * HH * S * D + sd;
    __half* o = g_Kh + (size_t)n * HH * S * D + sd;
    float e[HH]; float sum = 0.f;
#pragma unroll
    for (int h = 0; h < HH; h++) { e[h] = __expf(p[(size_t)h * S * D]); sum += e[h]; }
    float iv = 1.f / sum;
#pragma unroll
    for (int h = 0; h < HH; h++) o[(size_t)h * S * D] = __float2half_rn(e[h] * iv);
}

// ---------------------------------------------------------------------------
// pack mask bits
// ---------------------------------------------------------------------------
__global__ void k_pack_mask(const int* __restrict__ m) {
    int idx = blockIdx.x * blockDim.x + threadIdx.x;
    if (idx >= S * SW) return;
    int qq = idx >> 6, w = idx & 63;
    const int* p = m + (size_t)qq * S + w * 32;
    unsigned bits = 0;
#pragma unroll
    for (int b = 0; b < 32; b++) if (p[b] != 0) bits |= (1u << b);
    g_mb[idx] = bits;
}

// ---------------------------------------------------------------------------
// V convert: g_Vf = fp16(V)
// ---------------------------------------------------------------------------
__global__ void k_vhalf(const float* __restrict__ v) {
    int idx = blockIdx.x * blockDim.x + threadIdx.x;   // over quads
    if (idx >= NB * HH * S * D / 4) return;
    float4 f = *(const float4*)(v + (size_t)idx * 4);
    __half2 h01 = __floats2half2_rn(f.x, f.y);
    __half2 h23 = __floats2half2_rn(f.z, f.w);
    *(uint2*)(g_Vf + (size_t)idx * 4) = make_uint2(*(uint32_t*)&h01, *(uint32_t*)&h23);
}

// ---------------------------------------------------------------------------
// fused attention, cp.async double-buffered, fp16 MMA path
// ---------------------------------------------------------------------------
#define O_INVL 0
#define O_MB0  512
#define O_MB1  2560
#define O_KB0  4608
#define O_KB1  20992    /* also Q tile during prologue */
#define O_VH0  37376
#define O_VH1  53760
#define SMEM_T 70144

__global__ void __launch_bounds__(256, 2) k_attn(float* __restrict__ attn,
                                                 float* __restrict__ ctx) {
    extern __shared__ char smem[];
    const int tid = threadIdx.x, wid = tid >> 5, lid = tid & 31;
    const int g = lid >> 2, t = lid & 3;
    const int nh = blockIdx.y, q0 = blockIdx.x * 128;
    const uint32_t sb = smem_u32(smem);
    float* invl = (float*)(smem + O_INVL);

    const __half* Qg = g_Qh + ((size_t)nh * S + q0) * D;
    const __half* Kg = g_Kh + (size_t)nh * S * D;
    const __half* Vg = g_Vf + (size_t)nh * S * D;
    float* attnb = attn + (size_t)nh * S * S;

    // ---- prefetch K tile 0 + mask 0 into buf 0 (overlaps Q load/hoist) ----
    {
#pragma unroll
        for (int i = 0; i < 4; i++) {
            int idx = i * 256 + tid;
            int r = idx >> 3, s16 = idx & 7;
            cpa16(sb + O_KB0 + SWZ(r * 128 + s16 * 16), Kg + (size_t)r * 64 + s16 * 8);
        }
        if (tid < 128)
            cpa16(sb + O_MB0 + tid * 16, g_mb + (size_t)(q0 + tid) * SW);
        CPA_COMMIT();
    }

    // ---- load Q tile into KB1 region, hoist fragments, then recycle ----
#pragma unroll
    for (int i = 0; i < 4; i++) {
        int idx = i * 256 + tid;
        int r = idx >> 3, s16 = idx & 7;
        *(uint4*)(smem + O_KB1 + SWZ(r * 128 + s16 * 16)) =
            *(const uint4*)(Qg + (size_t)r * 64 + s16 * 8);
    }
    __syncthreads();
    uint32_t aQ[4][4];
#pragma unroll
    for (int kk = 0; kk < 4; kk++) {
        int rl = 16 * wid + (lid & 7) + (lid & 8);
        int c16 = kk * 2 + (lid >> 4);
        ldsm4(aQ[kk], sb + O_KB1 + SWZ(rl * 128 + c16 * 16));
    }
    __syncthreads();   // Q region now reusable as K buffer 1

    const int r0l = 16 * wid + g, r1l = r0l + 8;

    // ================= pass 1: row sums =================
    float rs0 = 0.f, rs1 = 0.f;
    for (int kt = 0; kt < 16; kt++) {
        CPA_WAIT0();
        __syncthreads();
        if (kt < 15) {   // prefetch kt+1
            int b = (kt + 1) & 1;
            uint32_t kb = b ? O_KB1 : O_KB0, mb = b ? O_MB1 : O_MB0;
#pragma unroll
            for (int i = 0; i < 4; i++) {
                int idx = i * 256 + tid;
                int r = idx >> 3, s16 = idx & 7;
                cpa16(sb + kb + SWZ(r * 128 + s16 * 16),
                      Kg + (size_t)((kt + 1) * 128 + r) * 64 + s16 * 8);
            }
            if (tid < 128)
                cpa16(sb + mb + tid * 16, g_mb + (size_t)(q0 + tid) * SW + (kt + 1) * 4);
            CPA_COMMIT();
        }
        const uint32_t kb = (kt & 1) ? O_KB1 : O_KB0;
        const uint32_t mb = (kt & 1) ? O_MB1 : O_MB0;

        uint4 mw0 = *(uint4*)(smem + mb + r0l * 16);
        uint4 mw1 = *(uint4*)(smem + mb + r1l * 16);
        unsigned m0a[4] = {mw0.x, mw0.y, mw0.z, mw0.w};
        unsigned m1a[4] = {mw1.x, mw1.y, mw1.z, mw1.w};

#pragma unroll
        for (int c = 0; c < 4; c++) {
            float acc4[4][4];
#pragma unroll
            for (int f4 = 0; f4 < 4; f4++) { acc4[f4][0] = acc4[f4][1] = acc4[f4][2] = acc4[f4][3] = 0.f; }
#pragma unroll
            for (int f4 = 0; f4 < 4; f4++) {
                int f = 4 * c + f4;
#pragma unroll
                for (int kp = 0; kp < 2; kp++) {
                    uint32_t b[4];
                    ldsm4(b, sb + kb + SWZ((f * 8 + (lid & 7)) * 128 + (kp * 4 + (lid >> 3)) * 16));
                    mma_fp(acc4[f4], aQ[2 * kp], b);
                    mma_fp(acc4[f4], aQ[2 * kp + 1], b + 2);
                }
            }
            unsigned w0 = m0a[c], w1 = m1a[c];
#pragma unroll
            for (int f4 = 0; f4 < 4; f4++) {
                int bit = 8 * f4 + 2 * t;
                if ((w0 >> bit) & 1)       rs0 += __expf(acc4[f4][0]);
                if ((w0 >> (bit + 1)) & 1) rs0 += __expf(acc4[f4][1]);
                if ((w1 >> bit) & 1)       rs1 += __expf(acc4[f4][2]);
                if ((w1 >> (bit + 1)) & 1) rs1 += __expf(acc4[f4][3]);
            }
        }
    }

    // ---- prefetch pass-2 tile 0 early (overlaps reduction) ----
    {
#pragma unroll
        for (int i = 0; i < 4; i++) {
            int idx = i * 256 + tid;
            int r = idx >> 3, s16 = idx & 7;
            uint32_t swo = SWZ(r * 128 + s16 * 16);
            size_t gofs = (size_t)r * 64 + s16 * 8;
            cpa16(sb + O_KB0 + swo, Kg + gofs);
            cpa16(sb + O_VH0 + swo, Vg + gofs);
        }
        if (tid < 128)
            cpa16(sb + O_MB0 + tid * 16, g_mb + (size_t)(q0 + tid) * SW);
        CPA_COMMIT();
    }

    rs0 += __shfl_xor_sync(0xffffffffu, rs0, 1);
    rs0 += __shfl_xor_sync(0xffffffffu, rs0, 2);
    rs1 += __shfl_xor_sync(0xffffffffu, rs1, 1);
    rs1 += __shfl_xor_sync(0xffffffffu, rs1, 2);
    if (t == 0) {
        invl[r0l] = rs0 > 0.f ? 1.f / rs0 : 0.f;
        invl[r1l] = rs1 > 0.f ? 1.f / rs1 : 0.f;
    }
    __syncthreads();
    const float iv0 = invl[r0l], iv1 = invl[r1l];

    // ================= pass 2: recompute + normalize + chunked GEMM2 ========
    float ctxa[8][4];
#pragma unroll
    for (int n = 0; n < 8; n++) { ctxa[n][0] = ctxa[n][1] = ctxa[n][2] = ctxa[n][3] = 0.f; }

    for (int kt = 0; kt < 16; kt++) {
        CPA_WAIT0();
        __syncthreads();
        if (kt < 15) {   // prefetch kt+1
            int b = (kt + 1) & 1;
            uint32_t kb = b ? O_KB1 : O_KB0, vh = b ? O_VH1 : O_VH0;
            uint32_t mb = b ? O_MB1 : O_MB0;
#pragma unroll
            for (int i = 0; i < 4; i++) {
                int idx = i * 256 + tid;
                int r = idx >> 3, s16 = idx & 7;
                uint32_t swo = SWZ(r * 128 + s16 * 16);
                size_t gofs = (size_t)((kt + 1) * 128 + r) * 64 + s16 * 8;
                cpa16(sb + kb + swo, Kg + gofs);
                cpa16(sb + vh + swo, Vg + gofs);
            }
            if (tid < 128)
                cpa16(sb + mb + tid * 16, g_mb + (size_t)(q0 + tid) * SW + (kt + 1) * 4);
            CPA_COMMIT();
        }
        const int bsel = kt & 1;
        const uint32_t kb  = bsel ? O_KB1 : O_KB0;
        const uint32_t vhb = bsel ? O_VH1 : O_VH0;
        const uint32_t mb  = bsel ? O_MB1 : O_MB0;

        uint4 mw0 = *(uint4*)(smem + mb + r0l * 16);
        uint4 mw1 = *(uint4*)(smem + mb + r1l * 16);
        unsigned m0a[4] = {mw0.x, mw0.y, mw0.z, mw0.w};
        unsigned m1a[4] = {mw1.x, mw1.y, mw1.z, mw1.w};

#pragma unroll
        for (int c = 0; c < 4; c++) {
            // --- GEMM1 for 4 fragments (32 attn cols) ---
            float acc4[4][4];
#pragma unroll
            for (int f4 = 0; f4 < 4; f4++) { acc4[f4][0] = acc4[f4][1] = acc4[f4][2] = acc4[f4][3] = 0.f; }
#pragma unroll
            for (int f4 = 0; f4 < 4; f4++) {
                int f = 4 * c + f4;
#pragma unroll
                for (int kp = 0; kp < 2; kp++) {
                    uint32_t b[4];
                    ldsm4(b, sb + kb + SWZ((f * 8 + (lid & 7)) * 128 + (kp * 4 + (lid >> 3)) * 16));
                    mma_fp(acc4[f4], aQ[2 * kp], b);
                    mma_fp(acc4[f4], aQ[2 * kp + 1], b + 2);
                }
            }
            // --- epilogue: masked exp, normalize, store, split-fp16 W frags ---
            unsigned w0 = m0a[c], w1 = m1a[c];
            uint32_t wh4[4][2], wl4[4][2];
#pragma unroll
            for (int f4 = 0; f4 < 4; f4++) {
                int bit = 8 * f4 + 2 * t;
                float e0 = ((w0 >> bit) & 1)       ? __expf(acc4[f4][0]) * iv0 : 0.f;
                float e1 = ((w0 >> (bit + 1)) & 1) ? __expf(acc4[f4][1]) * iv0 : 0.f;
                float e2 = ((w1 >> bit) & 1)       ? __expf(acc4[f4][2]) * iv1 : 0.f;
                float e3 = ((w1 >> (bit + 1)) & 1) ? __expf(acc4[f4][3]) * iv1 : 0.f;
                int col = kt * 128 + 32 * c + 8 * f4 + 2 * t;
                *(float2*)&attnb[(size_t)(q0 + r0l) * S + col] = make_float2(e0, e1);
                *(float2*)&attnb[(size_t)(q0 + r1l) * S + col] = make_float2(e2, e3);
                __half h0 = __float2half_rn(e0), h1 = __float2half_rn(e1);
                __half h2 = __float2half_rn(e2), h3 = __float2half_rn(e3);
                wh4[f4][0] = pack_h(h0, h1);
                wh4[f4][1] = pack_h(h2, h3);
                __half2 l01 = __floats2half2_rn(e0 - __half2float(h0), e1 - __half2float(h1));
                __half2 l23 = __floats2half2_rn(e2 - __half2float(h2), e3 - __half2float(h3));
                wl4[f4][0] = *(uint32_t*)&l01;
                wl4[f4][1] = *(uint32_t*)&l23;
            }
            // --- GEMM2 partial: ctx += W[:,32c..32c+31] @ V[32c..32c+31,:] ---
            uint32_t aH0[4] = {wh4[0][0], wh4[0][1], wh4[1][0], wh4[1][1]};
            uint32_t aH1[4] = {wh4[2][0], wh4[2][1], wh4[3][0], wh4[3][1]};
            uint32_t aL0[4] = {wl4[0][0], wl4[0][1], wl4[1][0], wl4[1][1]};
            uint32_t aL1[4] = {wl4[2][0], wl4[2][1], wl4[3][0], wl4[3][1]};
#pragma unroll
            for (int n8 = 0; n8 < 8; n8++) {
                uint32_t bh[4];
                ldsm4t(bh, sb + vhb + SWZ((c * 32 + lid) * 128 + n8 * 16));
                mma_fp(ctxa[n8], aH0, bh);
                mma_fp(ctxa[n8], aH1, bh + 2);
                mma_fp(ctxa[n8], aL0, bh);
                mma_fp(ctxa[n8], aL1, bh + 2);
            }
        }
    }

    // ---- ctx store ----
#pragma unroll
    for (int n8 = 0; n8 < 8; n8++) {
        int c = 8 * n8 + 2 * t;
        *(float2*)&ctx[((size_t)nh * S + q0 + r0l) * D + c] = make_float2(ctxa[n8][0], ctxa[n8][1]);
        *(float2*)&ctx[((size_t)nh * S + q0 + r1l) * D + c] = make_float2(ctxa[n8][2], ctxa[n8][3]);
    }
}

// ---------------------------------------------------------------------------
extern "C" void kernel_launch(void* const* d_in, const int* in_sizes, int n_in,
                              void* d_out, int out_size) {
    const float* q = (const float*)d_in[0];
    const float* k = (const float*)d_in[1];
    const float* v = (const float*)d_in[2];
    const int*   m = (const int*)d_in[3];

    float* ctx  = (float*)d_out;
    float* attn = (float*)d_out + CTX_ELEMS;

    cudaFuncSetAttribute(k_attn, cudaFuncAttributeMaxDynamicSharedMemorySize, SMEM_T);

    k_softmax_q<<<dim3(NH, 8), 256>>>(q);
    k_softmax_k<<<(NB * S * D + 255) / 256, 256>>>(k);
    k_pack_mask<<<(S * SW + 255) / 256, 256>>>(m);
    k_vhalf<<<(NB * HH * S * D / 4 + 255) / 256, 256>>>(v);
    k_attn<<<dim3(16, NH), 256, SMEM_T>>>(attn, ctx);
}